// round 1
// baseline (speedup 1.0000x reference)
#include <cuda_runtime.h>

// Problem constants
#define N_IN   8192
#define K_SEL  256
#define THREADS 1024
#define EPT    (N_IN / THREADS)   // 8 elements per thread
#define NBINS  256

__device__ __forceinline__ unsigned f2key(float x) {
    unsigned u = __float_as_uint(x);
    // order-preserving map: larger float -> larger unsigned
    return (u & 0x80000000u) ? ~u : (u | 0x80000000u);
}

__global__ __launch_bounds__(THREADS, 1)
void topk_hard_kernel(const float* __restrict__ logits,
                      const float* __restrict__ noise,
                      const float* __restrict__ smem_in,
                      float* __restrict__ out)
{
    const int b = blockIdx.x;
    const int t = threadIdx.x;
    const int lane = t & 31;
    const int wid  = t >> 5;

    const float* L = logits  + (size_t)b * N_IN;
    const float* G = noise   + (size_t)b * N_IN;
    const float* M = smem_in + (size_t)b * N_IN;
    float*       O = out     + (size_t)b * N_IN;

    __shared__ unsigned hist[NBINS];
    __shared__ int      warp_sums[32];
    __shared__ unsigned s_prefix;
    __shared__ int      s_kr;
    __shared__ int      s_digit;

    // ---- load: contiguous chunk of EPT floats per thread (2x float4 per array)
    const int base = t * EPT;
    float mem[EPT];
    unsigned key[EPT];
    {
        float4 l0 = *reinterpret_cast<const float4*>(L + base);
        float4 l1 = *reinterpret_cast<const float4*>(L + base + 4);
        float4 g0 = *reinterpret_cast<const float4*>(G + base);
        float4 g1 = *reinterpret_cast<const float4*>(G + base + 4);
        float4 m0 = *reinterpret_cast<const float4*>(M + base);
        float4 m1 = *reinterpret_cast<const float4*>(M + base + 4);
        float lv[EPT] = {l0.x,l0.y,l0.z,l0.w,l1.x,l1.y,l1.z,l1.w};
        float gv[EPT] = {g0.x,g0.y,g0.z,g0.w,g1.x,g1.y,g1.z,g1.w};
        float mv[EPT] = {m0.x,m0.y,m0.z,m0.w,m1.x,m1.y,m1.z,m1.w};
        #pragma unroll
        for (int j = 0; j < EPT; j++) {
            mem[j] = mv[j];
            float p = (lv[j] + gv[j]) + mv[j] * (-1000.0f);
            key[j] = f2key(p);
        }
    }

    if (t == 0) { s_prefix = 0u; s_kr = K_SEL; }
    __syncthreads();

    // ---- 4-pass radix select (8 bits / pass, descending)
    #pragma unroll
    for (int pass = 0; pass < 4; pass++) {
        const int shift = 24 - 8 * pass;
        if (t < NBINS) hist[t] = 0u;
        __syncthreads();

        const unsigned pmask = (pass == 0) ? 0u : (0xFFFFFFFFu << (shift + 8));
        const unsigned pref  = s_prefix;   // valid: synced above, written last pass

        #pragma unroll
        for (int j = 0; j < EPT; j++) {
            if ((key[j] & pmask) == pref)
                atomicAdd(&hist[(key[j] >> shift) & 0xFFu], 1u);
        }
        __syncthreads();

        // warp 0: find digit where descending cumulative count crosses s_kr
        if (t < 32) {
            const int hi = 255 - 8 * t;   // lane t covers digits [hi-7 .. hi], descending
            int sum = 0;
            #pragma unroll
            for (int j = 0; j < 8; j++) sum += (int)hist[hi - j];

            // inclusive scan over lanes (lane 0 = top digits)
            int v = sum;
            #pragma unroll
            for (int off = 1; off < 32; off *= 2) {
                int n = __shfl_up_sync(0xFFFFFFFFu, v, off);
                if (lane >= off) v += n;
            }
            const int excl = v - sum;  // count strictly above this lane's chunk
            const int krr = s_kr;
            __syncwarp();
            if (excl < krr && excl + sum >= krr) {
                int acc = excl;
                #pragma unroll
                for (int j = 0; j < 8; j++) {
                    const int h = (int)hist[hi - j];
                    if (acc + h >= krr) {
                        s_digit = hi - j;
                        s_kr    = krr - acc;  // residual rank within digit class
                        break;
                    }
                    acc += h;
                }
            }
        }
        __syncthreads();
        if (t == 0) s_prefix |= ((unsigned)s_digit) << shift;
        __syncthreads();
    }

    const unsigned thrKey = s_prefix;  // exact key of the K-th largest element
    const int r = s_kr;                // take r of the (>=1) keys equal to thrKey

    // ---- deterministic tie-break by index: block exclusive scan of equal-counts
    int local = 0;
    #pragma unroll
    for (int j = 0; j < EPT; j++) local += (key[j] == thrKey);

    int incl = local;
    #pragma unroll
    for (int off = 1; off < 32; off *= 2) {
        int n = __shfl_up_sync(0xFFFFFFFFu, incl, off);
        if (lane >= off) incl += n;
    }
    if (lane == 31) warp_sums[wid] = incl;
    __syncthreads();
    if (t < 32) {
        int v2 = warp_sums[t];
        int i2 = v2;
        #pragma unroll
        for (int off = 1; off < 32; off *= 2) {
            int n = __shfl_up_sync(0xFFFFFFFFu, i2, off);
            if (t >= off) i2 += n;
        }
        warp_sums[t] = i2 - v2;  // exclusive
    }
    __syncthreads();

    int rank = warp_sums[wid] + (incl - local);  // index-ordered rank among equals

    // ---- output: out = mem + one_hot(selected)
    float o[EPT];
    #pragma unroll
    for (int j = 0; j < EPT; j++) {
        bool sel;
        if (key[j] > thrKey)       sel = true;
        else if (key[j] == thrKey) { sel = (rank < r); rank++; }
        else                       sel = false;
        o[j] = mem[j] + (sel ? 1.0f : 0.0f);
    }
    *reinterpret_cast<float4*>(O + base)     = make_float4(o[0], o[1], o[2], o[3]);
    *reinterpret_cast<float4*>(O + base + 4) = make_float4(o[4], o[5], o[6], o[7]);
}

extern "C" void kernel_launch(void* const* d_in, const int* in_sizes, int n_in,
                              void* d_out, int out_size) {
    const float* logits = (const float*)d_in[0];
    const float* noise  = (const float*)d_in[1];
    const float* smem   = (const float*)d_in[2];
    float* out = (float*)d_out;

    const int B = in_sizes[0] / N_IN;
    topk_hard_kernel<<<B, THREADS>>>(logits, noise, smem, out);
}